// round 16
// baseline (speedup 1.0000x reference)
#include <cuda_runtime.h>
#include <math.h>

#define TT 512
#define PP 8
#define LL 64
#define HH 180
#define ROWS 16
#define NTHREADS 512
#define BATCH 2048

typedef unsigned long long u64;

// ---- transposed weight scratch (padded) ----
__device__ __align__(16) float g_WT_in  [72  * 192];   // [k][col], col pad 180->192
__device__ __align__(16) float g_WT_hp  [64  * 192];
__device__ __align__(16) float g_WT_gate[180 * 1088];  // cols 0..539 = W_ih, 544..1083 = W_hh
__device__ __align__(16) float g_WT_o1  [244 * 192];   // k permuted: k<64 -> cur(orig 180+k), else h(k-64)
__device__ __align__(16) float g_WT_o2  [180 * 64];

__global__ void prep_kernel(const float* __restrict__ W_in, const float* __restrict__ W_hp,
                            const float* __restrict__ W_ih, const float* __restrict__ W_hh,
                            const float* __restrict__ W_o1, const float* __restrict__ W_o2)
{
    int i = blockIdx.x * blockDim.x + threadIdx.x;
    const int S0 = 72*192, S1 = 64*192, S2 = 180*1088, S3 = 244*192, S4 = 180*64;
    if (i < S0) { int k = i/192, j = i%192; g_WT_in[i] = (j<180) ? W_in[j*72+k] : 0.f; return; }
    i -= S0;
    if (i < S1) { int k = i/192, j = i%192; g_WT_hp[i] = (j<180) ? W_hp[j*64+k] : 0.f; return; }
    i -= S1;
    if (i < S2) {
        int k = i/1088, j = i%1088;
        float v = 0.f;
        if (j < 540)                 v = W_ih[j*180+k];
        else if (j >= 544 && j < 1084) v = W_hh[(j-544)*180+k];
        g_WT_gate[i] = v; return;
    }
    i -= S2;
    if (i < S3) {
        int k = i/192, j = i%192;
        int ks = (k < 64) ? (180 + k) : (k - 64);
        g_WT_o1[i] = (j<180) ? W_o1[j*244+ks] : 0.f; return;
    }
    i -= S3;
    if (i < S4) { int k = i/64, j = i%64; g_WT_o2[i] = W_o2[j*180+k]; }
}

// ---- packed f32x2 helpers ----
__device__ __forceinline__ u64 pack2(float w) {
    u64 r; asm("mov.b64 %0, {%1, %1};" : "=l"(r) : "f"(w)); return r;
}
__device__ __forceinline__ void fma2(u64 &acc, u64 x, u64 w) {
    asm("fma.rn.f32x2 %0, %1, %2, %3;" : "=l"(acc) : "l"(x), "l"(w), "l"(acc));
}
__device__ __forceinline__ void unpack2(u64 v, float &lo, float &hi) {
    asm("mov.b64 {%0, %1}, %2;" : "=f"(lo), "=f"(hi) : "l"(v));
}
__device__ __forceinline__ float gelu_f(float x) {
    return 0.5f * x * (1.0f + erff(x * 0.70710678118654752440f));
}
__device__ __forceinline__ float sigm_f(float x) {
    return 1.0f / (1.0f + expf(-x));
}

// 16-col x 16-row warp tile. Lane: cb = lane&3 (4 cols each), rp = lane>>2 (2 rows each).
// X: activation dup buffer as u64 [K][16] (value duplicated in both halves).
// WT: [K][NPAD] scalar. Each FFMA2 = 1 row x 2 cols.
// DUP: write dst as dup u64 [col][16]; else scalar float [col][16].
template<int K, int NPAD, bool DUP, int ACT>
__device__ __forceinline__ void tile16(
    const u64* __restrict__ Xd, const float* __restrict__ WT,
    int col0, int cb, int rp,
    const float* __restrict__ bias, float* __restrict__ dst)
{
    const int c0 = col0 + cb * 4;
    const int r0 = rp * 2;
    const int wstride = NPAD / 4;                       // ulonglong2 per k-row
    const ulonglong2* wp = ((const ulonglong2*)WT) + (c0 >> 2);
    const ulonglong2* xp = ((const ulonglong2*)Xd) + rp;

    u64 a00 = 0, a01 = 0, a10 = 0, a11 = 0;
    ulonglong2 wb[4], xb[4];
#pragma unroll
    for (int u = 0; u < 4; ++u) { wb[u] = wp[u * wstride]; xb[u] = xp[u * 8]; }
    wp += 4 * wstride; xp += 32;

#pragma unroll 2
    for (int kb = 0; kb < K - 4; kb += 4) {
#pragma unroll
        for (int u = 0; u < 4; ++u) {
            ulonglong2 w = wb[u], x = xb[u];
            wb[u] = wp[u * wstride];
            xb[u] = xp[u * 8];
            fma2(a00, x.x, w.x); fma2(a01, x.y, w.x);
            fma2(a10, x.x, w.y); fma2(a11, x.y, w.y);
        }
        wp += 4 * wstride; xp += 32;
    }
#pragma unroll
    for (int u = 0; u < 4; ++u) {
        ulonglong2 w = wb[u], x = xb[u];
        fma2(a00, x.x, w.x); fma2(a01, x.y, w.x);
        fma2(a10, x.x, w.y); fma2(a11, x.y, w.y);
    }

    float v[2][2][2];   // [colpair][row][lo/hi]
    unpack2(a00, v[0][0][0], v[0][0][1]);
    unpack2(a01, v[0][1][0], v[0][1][1]);
    unpack2(a10, v[1][0][0], v[1][0][1]);
    unpack2(a11, v[1][1][0], v[1][1][1]);
#pragma unroll
    for (int cp = 0; cp < 2; ++cp)
#pragma unroll
        for (int rr = 0; rr < 2; ++rr)
#pragma unroll
            for (int hl = 0; hl < 2; ++hl) {
                int c = c0 + cp * 2 + hl;
                float val = v[cp][rr][hl] + bias[c];
                if (ACT == 1) val = gelu_f(val);
                if (DUP) ((u64*)dst)[c * 16 + (r0 + rr)] = pack2(val);
                else     dst[c * 16 + (r0 + rr)] = val;
            }
}

// SMEM layout (floats)
#define OFF_HC   0       // dup [256][16] u64 : cur rows 0..63, h rows 64..243, pad ..255  (8192 f)
#define OFF_CAT  8192    // dup [72][16] u64  (2304 f)  -- also reused as output stage (1024 f)
#define OFF_X    10496   // dup [192][16] u64 (6144 f)
#define OFF_O1   16640   // dup [192][16] u64 (6144 f)
#define OFF_G    22784   // scalar [1088][16] (17408 f)
#define OFF_BIAS 40192   // 1700
#define SMEM_FLOATS 41892

__global__ void __launch_bounds__(NTHREADS, 1)
latent_rnn_kernel(const float* __restrict__ phys,
                  const float* __restrict__ latents,
                  const float* __restrict__ b_in, const float* __restrict__ b_hp,
                  const float* __restrict__ b_ih, const float* __restrict__ b_hh,
                  const float* __restrict__ b_o1, const float* __restrict__ b_o2,
                  float* __restrict__ out)
{
    extern __shared__ float sm[];
    float* s_hc   = sm + OFF_HC;
    float* s_cat  = sm + OFF_CAT;
    float* s_x    = sm + OFF_X;
    float* s_o1   = sm + OFF_O1;
    float* s_g    = sm + OFF_G;
    float* s_bias = sm + OFF_BIAS;
    u64* hc64  = (u64*)s_hc;
    u64* cat64 = (u64*)s_cat;
    u64* x64   = (u64*)s_x;
    u64* o164  = (u64*)s_o1;

    const int tid  = threadIdx.x;
    const int w    = tid >> 5;
    const int lane = tid & 31;
    const int cb   = lane & 3;
    const int rp   = lane >> 2;
    const int r0b  = blockIdx.x * ROWS;

    // biases (padded with zeros to 1700)
    for (int i = tid; i < 1700; i += NTHREADS) {
        float v = 0.f;
        if (i < 180)       v = b_in[i];
        else if (i < 720)  v = b_ih[i - 180];
        else if (i < 1260) v = b_hh[i - 720];
        else if (i < 1440) v = b_o1[i - 1260];
        else if (i < 1504) v = b_o2[i - 1440];
        else if (i < 1684) v = b_hp[i - 1504];
        s_bias[i] = v;
    }
    // latents -> cur rows (dup) + h0 source (dup)
    for (int e = tid; e < LL * ROWS; e += NTHREADS) {
        int c = e >> 4, r = e & 15;
        u64 p = pack2(latents[(size_t)(r0b + r) * LL + c]);
        cat64[c * 16 + r] = p;
        hc64[c * 16 + r]  = p;
    }
    __syncthreads();

    // h0 = latents @ W_hp^T + b_hp -> h rows (dup), 12 tiles
    if (w < 12)
        tile16<64, 192, true, 0>(cat64, g_WT_hp, w * 16, cb, rp,
                                 s_bias + 1504, (float*)(hc64 + 64 * 16));
    __syncthreads();

    // ==================== time loop ====================
    for (int t = 0; t < TT; ++t) {
        // build cat = [phys_t(8) ; cur(64)] dup
        if (tid < 128) {
            int r = tid >> 3, p = tid & 7;
            cat64[p * 16 + r] = pack2(phys[((size_t)(r0b + r) * TT + t) * PP + p]);
        }
        for (int e = tid; e < LL * ROWS; e += NTHREADS) {
            int c = e >> 4, r = e & 15;
            cat64[(PP + c) * 16 + r] = hc64[c * 16 + r];
        }
        __syncthreads();

        // phase 1: x = gelu(cat @ W_in^T + b_in), N=192, 12 tiles
        if (w < 12)
            tile16<72, 192, true, 1>(cat64, g_WT_in, w * 16, cb, rp,
                                     s_bias, (float*)x64);
        __syncthreads();

        // phase 2 (gate): gi cols 0..539 (src x), gh cols 544..1083 (src h), 68 tiles
        for (int tl = w; tl < 68; tl += 16) {
            const u64* src = (tl < 34) ? x64 : (hc64 + 64 * 16);
            const float* bp = (tl < 34) ? (s_bias + 180) : (s_bias + 720 - 544);
            tile16<180, 1088, false, 0>(src, g_WT_gate, tl * 16, cb, rp, bp, s_g);
        }
        __syncthreads();

        // GRU elementwise: h_new (dup) in place
        for (int e = tid; e < HH * ROWS; e += NTHREADS) {
            int j = e >> 4, r = e & 15;
            float rr = sigm_f(s_g[j * 16 + r]          + s_g[(544 + j) * 16 + r]);
            float zz = sigm_f(s_g[(180 + j) * 16 + r]  + s_g[(724 + j) * 16 + r]);
            float nn = tanhf (s_g[(360 + j) * 16 + r]  + rr * s_g[(904 + j) * 16 + r]);
            float h  = s_hc[(64 + j) * 32 + r * 2];
            hc64[(64 + j) * 16 + r] = pack2((1.0f - zz) * nn + zz * h);
        }
        __syncthreads();

        // phase 3: o1 = gelu([cur;h] @ W_o1'^T + b_o1), K=244, N=192, 12 tiles
        if (w < 12)
            tile16<244, 192, true, 1>(hc64, g_WT_o1, w * 16, cb, rp,
                                      s_bias + 1260, (float*)o164);
        __syncthreads();

        // phase 4: delta = o1 @ W_o2^T + b_o2, cur update fused. 8 tiles of 8 cols.
        if (w < 8) {
            const int cb2 = lane & 1;
            const int r   = lane >> 1;
            const int c0  = w * 8 + cb2 * 4;
            const ulonglong2* wp = ((const ulonglong2*)g_WT_o2) + (c0 >> 2);
            const u64* xp = o164 + r;
            u64 a0 = 0, a1 = 0;
            ulonglong2 wb[4]; u64 xb[4];
#pragma unroll
            for (int u = 0; u < 4; ++u) { wb[u] = wp[u * 16]; xb[u] = xp[u * 16]; }
            wp += 64; xp += 64;
#pragma unroll 2
            for (int kb = 0; kb < 176; kb += 4) {
#pragma unroll
                for (int u = 0; u < 4; ++u) {
                    ulonglong2 ww = wb[u]; u64 xx = xb[u];
                    wb[u] = wp[u * 16]; xb[u] = xp[u * 16];
                    fma2(a0, xx, ww.x); fma2(a1, xx, ww.y);
                }
                wp += 64; xp += 64;
            }
#pragma unroll
            for (int u = 0; u < 4; ++u) {
                ulonglong2 ww = wb[u]; u64 xx = xb[u];
                fma2(a0, xx, ww.x); fma2(a1, xx, ww.y);
            }
            float dd[4];
            unpack2(a0, dd[0], dd[1]);
            unpack2(a1, dd[2], dd[3]);
#pragma unroll
            for (int j = 0; j < 4; ++j) {
                int c = c0 + j;
                float v   = dd[j] + s_bias[1440 + c];
                float cur = s_hc[c * 32 + r * 2];
                float cn  = fminf(fmaxf(cur + v, 0.0f), 1.0f);
                hc64[c * 16 + r] = pack2(cn);
                s_cat[r * 64 + c] = cn;   // output staging (s_cat rebuilt next iter)
            }
        }
        __syncthreads();

        // coalesced output store
        for (int e = tid; e < LL * ROWS; e += NTHREADS) {
            int r = e >> 6, l = e & 63;
            out[((size_t)(r0b + r) * TT + t) * LL + l] = s_cat[e];
        }
        __syncthreads();
    }
}

extern "C" void kernel_launch(void* const* d_in, const int* in_sizes, int n_in,
                              void* d_out, int out_size)
{
    const float* phys    = (const float*)d_in[0];
    const float* latents = (const float*)d_in[1];
    const float* W_in    = (const float*)d_in[2];
    const float* b_in    = (const float*)d_in[3];
    const float* W_hp    = (const float*)d_in[4];
    const float* b_hp    = (const float*)d_in[5];
    const float* W_ih    = (const float*)d_in[6];
    const float* b_ih    = (const float*)d_in[7];
    const float* W_hh    = (const float*)d_in[8];
    const float* b_hh    = (const float*)d_in[9];
    const float* W_o1    = (const float*)d_in[10];
    const float* b_o1    = (const float*)d_in[11];
    const float* W_o2    = (const float*)d_in[12];
    const float* b_o2    = (const float*)d_in[13];
    float* out = (float*)d_out;

    const int total = 72*192 + 64*192 + 180*1088 + 244*192 + 180*64;
    prep_kernel<<<(total + 255) / 256, 256>>>(W_in, W_hp, W_ih, W_hh, W_o1, W_o2);

    size_t smem = (size_t)SMEM_FLOATS * sizeof(float);
    cudaFuncSetAttribute(latent_rnn_kernel,
                         cudaFuncAttributeMaxDynamicSharedMemorySize, (int)smem);
    latent_rnn_kernel<<<BATCH / ROWS, NTHREADS, smem>>>(
        phys, latents, b_in, b_hp, b_ih, b_hh, b_o1, b_o2, out);
}